// round 6
// baseline (speedup 1.0000x reference)
#include <cuda_runtime.h>
#include <cstdint>

// ---------------- problem constants ----------------
#define SEQ   4096
#define HD    64
#define NH    4
#define BM    128          // s rows per CTA
#define BN    64           // t cols per iteration
#define NTH   256
#define ITERS (SEQ/BN)     // 64

// smem strides (floats)
#define SQ 132             // Qs/Ks/Vs row stride (128+4) -> conflict-free frag loads
#define SP 68              // Ps row stride (64+4)

#define QS_OFF 0
#define KS_OFF (BM*SQ)
#define VS_OFF (KS_OFF + BN*SQ)
#define PS_OFF (VS_OFF + BN*SQ)
#define SMEM_FLOATS (PS_OFF + BM*SP)
#define SMEM_BYTES (SMEM_FLOATS*4)   // 169984 bytes

// ---------------- device scratch ----------------
__device__ unsigned g_mask_bits[SEQ * (SEQ / 32)];   // 2 MB packed mask
__device__ float    g_v1sum[NH * HD];                // sum_t V[1,h,t,d]

// ---------------- helpers ----------------
__device__ __forceinline__ float to_tf32(float x) {
    float y; asm("cvt.rna.tf32.f32 %0, %1;" : "=f"(y) : "f"(x)); return y;
}
__device__ __forceinline__ float ex2_fast(float x) {
    float y; asm("ex2.approx.f32 %0, %1;" : "=f"(y) : "f"(x)); return y;
}
__device__ __forceinline__ float rcp_fast(float x) {
    float y; asm("rcp.approx.f32 %0, %1;" : "=f"(y) : "f"(x)); return y;
}
__device__ __forceinline__ float sigp(float d) {
    // p0 = 1/(1+exp(-0.125*d)) ; C = -0.125*log2(e)
    const float C = -0.18033688011111652f;
    return rcp_fast(1.0f + ex2_fast(d * C));
}

#define MMA_TF32(d, a, b) asm volatile( \
    "mma.sync.aligned.m16n8k8.row.col.f32.tf32.tf32.f32 " \
    "{%0,%1,%2,%3}, {%4,%5,%6,%7}, {%8,%9}, {%0,%1,%2,%3};" \
    : "+f"((d)[0]), "+f"((d)[1]), "+f"((d)[2]), "+f"((d)[3]) \
    : "r"(__float_as_uint((a)[0])), "r"(__float_as_uint((a)[1])), \
      "r"(__float_as_uint((a)[2])), "r"(__float_as_uint((a)[3])), \
      "r"(__float_as_uint((b)[0])), "r"(__float_as_uint((b)[1])))

// ---------------- prologue kernels ----------------
__global__ void pack_mask_kernel(const int* __restrict__ mask) {
    int w = blockIdx.x * blockDim.x + threadIdx.x;      // 0 .. SEQ*128-1
    const int4* src = (const int4*)(mask + (size_t)w * 32);
    unsigned bits = 0;
    #pragma unroll
    for (int g = 0; g < 8; g++) {
        int4 v = src[g];
        bits |= (v.x != 0 ? 1u : 0u) << (g * 4 + 0);
        bits |= (v.y != 0 ? 1u : 0u) << (g * 4 + 1);
        bits |= (v.z != 0 ? 1u : 0u) << (g * 4 + 2);
        bits |= (v.w != 0 ? 1u : 0u) << (g * 4 + 3);
    }
    g_mask_bits[w] = bits;
}

__global__ void v1sum_kernel(const float* __restrict__ v) {
    __shared__ float red[256];
    int h = blockIdx.x;
    int d = threadIdx.x & 63;
    int part = threadIdx.x >> 6;
    float s = 0.f;
    for (int t = part; t < SEQ; t += 4)
        s += v[(((size_t)NH + h) * SEQ + t) * HD + d];   // b=1
    red[threadIdx.x] = s;
    __syncthreads();
    if (part == 0)
        g_v1sum[h * HD + d] = red[d] + red[64 + d] + red[128 + d] + red[192 + d];
}

// ---------------- main kernel ----------------
__global__ __launch_bounds__(NTH, 1)
void sdpa_mma_kernel(const float* __restrict__ q,
                     const float* __restrict__ k,
                     const float* __restrict__ v,
                     float* __restrict__ out,
                     float* __restrict__ attn)
{
    extern __shared__ float sm[];
    float* Qs = sm + QS_OFF;   // [128][SQ]  cols 0:64 = q0, 64:128 = q1
    float* Ks = sm + KS_OFF;   // [64][SQ]   cols 0:64 = k0, 64:128 = -k1
    float* Vs = sm + VS_OFF;   // [64][SQ]   cols 0:64 = v0, 64:128 = v1  ([t][n])
    float* Ps = sm + PS_OFF;   // [128][SP]  p0 (tf32)

    const int h   = blockIdx.y;
    const int s0  = blockIdx.x * BM;
    const int tid = threadIdx.x;
    const int w   = tid >> 5;
    const int lane = tid & 31;
    const int gr  = lane >> 2;     // group id (0..7)
    const int ct  = lane & 3;      // thread-in-group
    const int wm  = w & 3;         // warp m-block (32 rows)
    const int wn  = w >> 2;        // warp n-block

    // ---- stage Q (once): [128 rows][128 cols], tf32 ----
    for (int i = tid; i < BM * 32; i += NTH) {
        int row = i >> 5;
        int c4  = i & 31;
        int b   = c4 >> 4;
        int d4  = c4 & 15;
        float4 val = *(const float4*)(q + (((size_t)b * NH + h) * SEQ + s0 + row) * HD + d4 * 4);
        float4 o;
        o.x = to_tf32(val.x); o.y = to_tf32(val.y); o.z = to_tf32(val.z); o.w = to_tf32(val.w);
        *(float4*)(Qs + row * SQ + c4 * 4) = o;
    }

    // ---- persistent O accumulators: warp covers rows wm*32..+32, cols wn*64..+64
    float oc[2][8][4];
    #pragma unroll
    for (int mt = 0; mt < 2; mt++)
        #pragma unroll
        for (int nt = 0; nt < 8; nt++)
            #pragma unroll
            for (int u = 0; u < 4; u++) oc[mt][nt][u] = 0.f;

    for (int it = 0; it < ITERS; ++it) {
        const int t0 = it * BN;
        __syncthreads();   // Ks/Vs/Ps free

        // ---- stage K tile (sign-flipped b=1) and V tile ----
        for (int i = tid; i < BN * 32; i += NTH) {
            int t  = i >> 5;
            int c4 = i & 31;
            int b  = c4 >> 4;
            int d4 = c4 & 15;
            size_t gidx = (((size_t)b * NH + h) * SEQ + t0 + t) * HD + d4 * 4;
            float sgn = b ? -1.f : 1.f;
            float4 kv = *(const float4*)(k + gidx);
            float4 ko;
            ko.x = to_tf32(sgn * kv.x); ko.y = to_tf32(sgn * kv.y);
            ko.z = to_tf32(sgn * kv.z); ko.w = to_tf32(sgn * kv.w);
            *(float4*)(Ks + t * SQ + c4 * 4) = ko;
            float4 vv = *(const float4*)(v + gidx);
            float4 vo;
            vo.x = to_tf32(vv.x); vo.y = to_tf32(vv.y);
            vo.z = to_tf32(vv.z); vo.w = to_tf32(vv.w);
            *(float4*)(Vs + t * SQ + c4 * 4) = vo;
        }
        __syncthreads();

        // ---- MMA1: Delta[128][64] = Qc * Kc^T ; warp tile 32x32 ----
        float sc[2][4][4];
        #pragma unroll
        for (int mt = 0; mt < 2; mt++)
            #pragma unroll
            for (int nt = 0; nt < 4; nt++)
                #pragma unroll
                for (int u = 0; u < 4; u++) sc[mt][nt][u] = 0.f;

        #pragma unroll
        for (int kk = 0; kk < 16; kk++) {
            const int k0 = kk * 8;
            float a[2][4];
            #pragma unroll
            for (int mt = 0; mt < 2; mt++) {
                int r = wm * 32 + mt * 16 + gr;
                a[mt][0] = Qs[r * SQ + k0 + ct];
                a[mt][1] = Qs[(r + 8) * SQ + k0 + ct];
                a[mt][2] = Qs[r * SQ + k0 + ct + 4];
                a[mt][3] = Qs[(r + 8) * SQ + k0 + ct + 4];
            }
            float bfr[4][2];
            #pragma unroll
            for (int nt = 0; nt < 4; nt++) {
                int t = wn * 32 + nt * 8 + gr;
                bfr[nt][0] = Ks[t * SQ + k0 + ct];
                bfr[nt][1] = Ks[t * SQ + k0 + ct + 4];
            }
            #pragma unroll
            for (int mt = 0; mt < 2; mt++)
                #pragma unroll
                for (int nt = 0; nt < 4; nt++)
                    MMA_TF32(sc[mt][nt], a[mt], bfr[nt]);
        }

        // ---- epilogue: sigmoid + mask ; write attn (b0,b1) ; stage P ----
        unsigned mw[4];
        #pragma unroll
        for (int j = 0; j < 4; j++)
            mw[j] = g_mask_bits[(size_t)(s0 + wm * 32 + j * 8 + gr) * 128 + (t0 >> 5) + wn];

        float* attn1 = attn + (size_t)NH * SEQ * SEQ;
        #pragma unroll
        for (int mt = 0; mt < 2; mt++) {
            int r = wm * 32 + mt * 16 + gr;
            unsigned m0 = mw[mt * 2], m1 = mw[mt * 2 + 1];
            #pragma unroll
            for (int nt = 0; nt < 4; nt++) {
                int cl = nt * 8 + ct * 2;          // col within warp's 32
                float* s = sc[mt][nt];
                float p00 = ((m0 >> cl) & 1)       ? 0.5f : sigp(s[0]);
                float p01 = ((m0 >> (cl + 1)) & 1) ? 0.5f : sigp(s[1]);
                float p10 = ((m1 >> cl) & 1)       ? 0.5f : sigp(s[2]);
                float p11 = ((m1 >> (cl + 1)) & 1) ? 0.5f : sigp(s[3]);

                int pc = wn * 32 + cl;
                float2 t0v = make_float2(to_tf32(p00), to_tf32(p01));
                float2 t1v = make_float2(to_tf32(p10), to_tf32(p11));
                *(float2*)(Ps + r * SP + pc)       = t0v;
                *(float2*)(Ps + (r + 8) * SP + pc) = t1v;

                size_t ab = ((size_t)h * SEQ + s0 + r) * SEQ + t0 + pc;
                *(float2*)(attn  + ab)            = make_float2(p00, p01);
                *(float2*)(attn  + ab + 8 * SEQ)  = make_float2(p10, p11);
                *(float2*)(attn1 + ab)            = make_float2(1.f - p00, 1.f - p01);
                *(float2*)(attn1 + ab + 8 * SEQ)  = make_float2(1.f - p10, 1.f - p11);
            }
        }
        __syncthreads();   // Ps visible

        // ---- MMA2: O[128][128] += P0 * [V0|V1] ; warp tile 32x64 ----
        #pragma unroll
        for (int kk = 0; kk < 8; kk++) {
            const int k0 = kk * 8;
            float a[2][4];
            #pragma unroll
            for (int mt = 0; mt < 2; mt++) {
                int r = wm * 32 + mt * 16 + gr;
                a[mt][0] = Ps[r * SP + k0 + ct];
                a[mt][1] = Ps[(r + 8) * SP + k0 + ct];
                a[mt][2] = Ps[r * SP + k0 + ct + 4];
                a[mt][3] = Ps[(r + 8) * SP + k0 + ct + 4];
            }
            float bfr[8][2];
            #pragma unroll
            for (int nt = 0; nt < 8; nt++) {
                int n = wn * 64 + nt * 8 + gr;
                bfr[nt][0] = Vs[(k0 + ct) * SQ + n];
                bfr[nt][1] = Vs[(k0 + ct + 4) * SQ + n];
            }
            #pragma unroll
            for (int mt = 0; mt < 2; mt++)
                #pragma unroll
                for (int nt = 0; nt < 8; nt++)
                    MMA_TF32(oc[mt][nt], a[mt], bfr[nt]);
        }
    }

    // ---- final out write: wn=0 -> b0 = acc ; wn=1 -> b1 = v1sum - acc ----
    const float* vs = g_v1sum + h * HD;
    #pragma unroll
    for (int mt = 0; mt < 2; mt++) {
        int r = s0 + wm * 32 + mt * 16 + gr;
        #pragma unroll
        for (int nt = 0; nt < 8; nt++) {
            int n = wn * 64 + nt * 8 + ct * 2;   // 0..127
            int b = n >> 6;
            int d = n & 63;
            float* c = oc[mt][nt];
            float2 w0, w1;
            if (b == 0) {
                w0 = make_float2(c[0], c[1]);
                w1 = make_float2(c[2], c[3]);
            } else {
                w0 = make_float2(vs[d] - c[0], vs[d + 1] - c[1]);
                w1 = make_float2(vs[d] - c[2], vs[d + 1] - c[3]);
            }
            size_t ob = (((size_t)b * NH + h) * SEQ + r) * HD + d;
            *(float2*)(out + ob)            = w0;
            *(float2*)(out + ob + 8 * HD)   = w1;
        }
    }
}

// ---------------- launcher ----------------
extern "C" void kernel_launch(void* const* d_in, const int* in_sizes, int n_in,
                              void* d_out, int out_size)
{
    const float* q    = (const float*)d_in[0];
    const float* k    = (const float*)d_in[1];
    const float* v    = (const float*)d_in[2];
    const int*   mask = (const int*)  d_in[3];

    float* out  = (float*)d_out;
    float* attn = out + (size_t)2 * NH * SEQ * HD;

    pack_mask_kernel<<<SEQ * 128 / 256, 256>>>(mask);
    v1sum_kernel<<<NH, 256>>>(v);

    cudaFuncSetAttribute(sdpa_mma_kernel,
                         cudaFuncAttributeMaxDynamicSharedMemorySize, SMEM_BYTES);
    dim3 grid(SEQ / BM, NH);
    sdpa_mma_kernel<<<grid, NTH, SMEM_BYTES>>>(q, k, v, out, attn);
}

// round 7
// speedup vs baseline: 1.0034x; 1.0034x over previous
#include <cuda_runtime.h>
#include <cstdint>

// ---------------- problem constants ----------------
#define SEQ   4096
#define HD    64
#define NH    4
#define BM    128          // s rows per CTA
#define BN    64           // t cols per iteration
#define NTH   256
#define ITERS (SEQ/BN)     // 64

// smem strides (floats)
#define SQ 132             // Qs/Ks/Vs row stride (128+4) -> conflict-free frag loads
#define SP 68              // Ps row stride (64+4)

#define QS_OFF 0
#define KS_OFF (BM*SQ)
#define VS_OFF (KS_OFF + BN*SQ)
#define PS_OFF (VS_OFF + BN*SQ)
#define SMEM_FLOATS (PS_OFF + BM*SP)
#define SMEM_BYTES (SMEM_FLOATS*4)   // 169984 bytes

// ---------------- device scratch ----------------
__device__ unsigned g_mask_bits[SEQ * (SEQ / 32)];   // 2 MB packed mask
__device__ float    g_v1sum[NH * HD];                // sum_t V[1,h,t,d]

// ---------------- helpers ----------------
__device__ __forceinline__ float to_tf32(float x) {
    float y; asm("cvt.rna.tf32.f32 %0, %1;" : "=f"(y) : "f"(x)); return y;
}
__device__ __forceinline__ float ex2_fast(float x) {
    float y; asm("ex2.approx.f32 %0, %1;" : "=f"(y) : "f"(x)); return y;
}
__device__ __forceinline__ float rcp_fast(float x) {
    float y; asm("rcp.approx.f32 %0, %1;" : "=f"(y) : "f"(x)); return y;
}
__device__ __forceinline__ float sigp(float d) {
    // p0 = 1/(1+exp(-0.125*d)) ; C = -0.125*log2(e)
    const float C = -0.18033688011111652f;
    return rcp_fast(1.0f + ex2_fast(d * C));
}

#define MMA_TF32(d, a, b) asm volatile( \
    "mma.sync.aligned.m16n8k8.row.col.f32.tf32.tf32.f32 " \
    "{%0,%1,%2,%3}, {%4,%5,%6,%7}, {%8,%9}, {%0,%1,%2,%3};" \
    : "+f"((d)[0]), "+f"((d)[1]), "+f"((d)[2]), "+f"((d)[3]) \
    : "r"(__float_as_uint((a)[0])), "r"(__float_as_uint((a)[1])), \
      "r"(__float_as_uint((a)[2])), "r"(__float_as_uint((a)[3])), \
      "r"(__float_as_uint((b)[0])), "r"(__float_as_uint((b)[1])))

// ---------------- prologue kernels ----------------
__global__ void pack_mask_kernel(const int* __restrict__ mask) {
    int w = blockIdx.x * blockDim.x + threadIdx.x;      // 0 .. SEQ*128-1
    const int4* src = (const int4*)(mask + (size_t)w * 32);
    unsigned bits = 0;
    #pragma unroll
    for (int g = 0; g < 8; g++) {
        int4 v = src[g];
        bits |= (v.x != 0 ? 1u : 0u) << (g * 4 + 0);
        bits |= (v.y != 0 ? 1u : 0u) << (g * 4 + 1);
        bits |= (v.z != 0 ? 1u : 0u) << (g * 4 + 2);
        bits |= (v.w != 0 ? 1u : 0u) << (g * 4 + 3);
    }
    g_mask_bits[w] = bits;
}

__global__ void v1sum_kernel(const float* __restrict__ v) {
    __shared__ float red[256];
    int h = blockIdx.x;
    int d = threadIdx.x & 63;
    int part = threadIdx.x >> 6;
    float s = 0.f;
    for (int t = part; t < SEQ; t += 4)
        s += v[(((size_t)NH + h) * SEQ + t) * HD + d];   // b=1
    red[threadIdx.x] = s;
    __syncthreads();
    if (part == 0)
        g_v1sum[h * HD + d] = red[d] + red[64 + d] + red[128 + d] + red[192 + d];
}

// ---------------- main kernel ----------------
__global__ __launch_bounds__(NTH, 1)
void sdpa_mma_kernel(const float* __restrict__ q,
                     const float* __restrict__ k,
                     const float* __restrict__ v,
                     float* __restrict__ out,
                     float* __restrict__ attn)
{
    extern __shared__ float sm[];
    float* Qs = sm + QS_OFF;   // [128][SQ]  cols 0:64 = q0, 64:128 = q1
    float* Ks = sm + KS_OFF;   // [64][SQ]   cols 0:64 = k0, 64:128 = -k1
    float* Vs = sm + VS_OFF;   // [64][SQ]   cols 0:64 = v0, 64:128 = v1  ([t][n])
    float* Ps = sm + PS_OFF;   // [128][SP]  p0 (tf32)

    const int h   = blockIdx.y;
    const int s0  = blockIdx.x * BM;
    const int tid = threadIdx.x;
    const int w   = tid >> 5;
    const int lane = tid & 31;
    const int gr  = lane >> 2;     // group id (0..7)
    const int ct  = lane & 3;      // thread-in-group
    const int wm  = w & 3;         // warp m-block (32 rows)
    const int wn  = w >> 2;        // warp n-block

    // ---- stage Q (once): [128 rows][128 cols], tf32 ----
    for (int i = tid; i < BM * 32; i += NTH) {
        int row = i >> 5;
        int c4  = i & 31;
        int b   = c4 >> 4;
        int d4  = c4 & 15;
        float4 val = *(const float4*)(q + (((size_t)b * NH + h) * SEQ + s0 + row) * HD + d4 * 4);
        float4 o;
        o.x = to_tf32(val.x); o.y = to_tf32(val.y); o.z = to_tf32(val.z); o.w = to_tf32(val.w);
        *(float4*)(Qs + row * SQ + c4 * 4) = o;
    }

    // ---- persistent O accumulators: warp covers rows wm*32..+32, cols wn*64..+64
    float oc[2][8][4];
    #pragma unroll
    for (int mt = 0; mt < 2; mt++)
        #pragma unroll
        for (int nt = 0; nt < 8; nt++)
            #pragma unroll
            for (int u = 0; u < 4; u++) oc[mt][nt][u] = 0.f;

    for (int it = 0; it < ITERS; ++it) {
        const int t0 = it * BN;
        __syncthreads();   // Ks/Vs/Ps free

        // ---- stage K tile (sign-flipped b=1) and V tile ----
        for (int i = tid; i < BN * 32; i += NTH) {
            int t  = i >> 5;
            int c4 = i & 31;
            int b  = c4 >> 4;
            int d4 = c4 & 15;
            size_t gidx = (((size_t)b * NH + h) * SEQ + t0 + t) * HD + d4 * 4;
            float sgn = b ? -1.f : 1.f;
            float4 kv = *(const float4*)(k + gidx);
            float4 ko;
            ko.x = to_tf32(sgn * kv.x); ko.y = to_tf32(sgn * kv.y);
            ko.z = to_tf32(sgn * kv.z); ko.w = to_tf32(sgn * kv.w);
            *(float4*)(Ks + t * SQ + c4 * 4) = ko;
            float4 vv = *(const float4*)(v + gidx);
            float4 vo;
            vo.x = to_tf32(vv.x); vo.y = to_tf32(vv.y);
            vo.z = to_tf32(vv.z); vo.w = to_tf32(vv.w);
            *(float4*)(Vs + t * SQ + c4 * 4) = vo;
        }
        __syncthreads();

        // ---- MMA1: Delta[128][64] = Qc * Kc^T ; warp tile 32x32 ----
        float sc[2][4][4];
        #pragma unroll
        for (int mt = 0; mt < 2; mt++)
            #pragma unroll
            for (int nt = 0; nt < 4; nt++)
                #pragma unroll
                for (int u = 0; u < 4; u++) sc[mt][nt][u] = 0.f;

        #pragma unroll
        for (int kk = 0; kk < 16; kk++) {
            const int k0 = kk * 8;
            float a[2][4];
            #pragma unroll
            for (int mt = 0; mt < 2; mt++) {
                int r = wm * 32 + mt * 16 + gr;
                a[mt][0] = Qs[r * SQ + k0 + ct];
                a[mt][1] = Qs[(r + 8) * SQ + k0 + ct];
                a[mt][2] = Qs[r * SQ + k0 + ct + 4];
                a[mt][3] = Qs[(r + 8) * SQ + k0 + ct + 4];
            }
            float bfr[4][2];
            #pragma unroll
            for (int nt = 0; nt < 4; nt++) {
                int t = wn * 32 + nt * 8 + gr;
                bfr[nt][0] = Ks[t * SQ + k0 + ct];
                bfr[nt][1] = Ks[t * SQ + k0 + ct + 4];
            }
            #pragma unroll
            for (int mt = 0; mt < 2; mt++)
                #pragma unroll
                for (int nt = 0; nt < 4; nt++)
                    MMA_TF32(sc[mt][nt], a[mt], bfr[nt]);
        }

        // ---- epilogue: sigmoid + mask ; write attn (b0,b1) ; stage P ----
        unsigned mw[4];
        #pragma unroll
        for (int j = 0; j < 4; j++)
            mw[j] = g_mask_bits[(size_t)(s0 + wm * 32 + j * 8 + gr) * 128 + (t0 >> 5) + wn];

        float* attn1 = attn + (size_t)NH * SEQ * SEQ;
        #pragma unroll
        for (int mt = 0; mt < 2; mt++) {
            int r = wm * 32 + mt * 16 + gr;
            unsigned m0 = mw[mt * 2], m1 = mw[mt * 2 + 1];
            #pragma unroll
            for (int nt = 0; nt < 4; nt++) {
                int cl = nt * 8 + ct * 2;          // col within warp's 32
                float* s = sc[mt][nt];
                float p00 = ((m0 >> cl) & 1)       ? 0.5f : sigp(s[0]);
                float p01 = ((m0 >> (cl + 1)) & 1) ? 0.5f : sigp(s[1]);
                float p10 = ((m1 >> cl) & 1)       ? 0.5f : sigp(s[2]);
                float p11 = ((m1 >> (cl + 1)) & 1) ? 0.5f : sigp(s[3]);

                int pc = wn * 32 + cl;
                float2 t0v = make_float2(to_tf32(p00), to_tf32(p01));
                float2 t1v = make_float2(to_tf32(p10), to_tf32(p11));
                *(float2*)(Ps + r * SP + pc)       = t0v;
                *(float2*)(Ps + (r + 8) * SP + pc) = t1v;

                size_t ab = ((size_t)h * SEQ + s0 + r) * SEQ + t0 + pc;
                *(float2*)(attn  + ab)            = make_float2(p00, p01);
                *(float2*)(attn  + ab + 8 * SEQ)  = make_float2(p10, p11);
                *(float2*)(attn1 + ab)            = make_float2(1.f - p00, 1.f - p01);
                *(float2*)(attn1 + ab + 8 * SEQ)  = make_float2(1.f - p10, 1.f - p11);
            }
        }
        __syncthreads();   // Ps visible

        // ---- MMA2: O[128][128] += P0 * [V0|V1] ; warp tile 32x64 ----
        #pragma unroll
        for (int kk = 0; kk < 8; kk++) {
            const int k0 = kk * 8;
            float a[2][4];
            #pragma unroll
            for (int mt = 0; mt < 2; mt++) {
                int r = wm * 32 + mt * 16 + gr;
                a[mt][0] = Ps[r * SP + k0 + ct];
                a[mt][1] = Ps[(r + 8) * SP + k0 + ct];
                a[mt][2] = Ps[r * SP + k0 + ct + 4];
                a[mt][3] = Ps[(r + 8) * SP + k0 + ct + 4];
            }
            float bfr[8][2];
            #pragma unroll
            for (int nt = 0; nt < 8; nt++) {
                int n = wn * 64 + nt * 8 + gr;
                bfr[nt][0] = Vs[(k0 + ct) * SQ + n];
                bfr[nt][1] = Vs[(k0 + ct + 4) * SQ + n];
            }
            #pragma unroll
            for (int mt = 0; mt < 2; mt++)
                #pragma unroll
                for (int nt = 0; nt < 8; nt++)
                    MMA_TF32(oc[mt][nt], a[mt], bfr[nt]);
        }
    }

    // ---- final out write: wn=0 -> b0 = acc ; wn=1 -> b1 = v1sum - acc ----
    const float* vs = g_v1sum + h * HD;
    #pragma unroll
    for (int mt = 0; mt < 2; mt++) {
        int r = s0 + wm * 32 + mt * 16 + gr;
        #pragma unroll
        for (int nt = 0; nt < 8; nt++) {
            int n = wn * 64 + nt * 8 + ct * 2;   // 0..127
            int b = n >> 6;
            int d = n & 63;
            float* c = oc[mt][nt];
            float2 w0, w1;
            if (b == 0) {
                w0 = make_float2(c[0], c[1]);
                w1 = make_float2(c[2], c[3]);
            } else {
                w0 = make_float2(vs[d] - c[0], vs[d + 1] - c[1]);
                w1 = make_float2(vs[d] - c[2], vs[d + 1] - c[3]);
            }
            size_t ob = (((size_t)b * NH + h) * SEQ + r) * HD + d;
            *(float2*)(out + ob)            = w0;
            *(float2*)(out + ob + 8 * HD)   = w1;
        }
    }
}

// ---------------- launcher ----------------
extern "C" void kernel_launch(void* const* d_in, const int* in_sizes, int n_in,
                              void* d_out, int out_size)
{
    const float* q    = (const float*)d_in[0];
    const float* k    = (const float*)d_in[1];
    const float* v    = (const float*)d_in[2];
    const int*   mask = (const int*)  d_in[3];

    float* out  = (float*)d_out;
    float* attn = out + (size_t)2 * NH * SEQ * HD;

    pack_mask_kernel<<<SEQ * 128 / 256, 256>>>(mask);
    v1sum_kernel<<<NH, 256>>>(v);

    cudaFuncSetAttribute(sdpa_mma_kernel,
                         cudaFuncAttributeMaxDynamicSharedMemorySize, SMEM_BYTES);
    dim3 grid(SEQ / BM, NH);
    sdpa_mma_kernel<<<grid, NTH, SMEM_BYTES>>>(q, k, v, out, attn);
}

// round 8
// speedup vs baseline: 1.1866x; 1.1825x over previous
#include <cuda_runtime.h>
#include <cstdint>

// ---------------- problem constants ----------------
#define SEQ   4096
#define HD    64
#define NH    4
#define BM    128          // s rows per CTA
#define BN    64           // t cols per iteration
#define NTH   512
#define ITERS (SEQ/BN)     // 64

// smem strides (floats)
#define SQ 132             // Qs/Ks row stride  (≡4 mod 32 -> 4gr+ct conflict-free)
#define SV 136             // Vs row stride     (≡8 mod 32 -> 8ct+gr conflict-free)
#define SP 68              // Ps row stride     (≡4 mod 32)

#define QS_OFF 0
#define KS_OFF (BM*SQ)                       // 16896
#define VS_OFF (KS_OFF + BN*SQ)              // 25344
#define PS_OFF (VS_OFF + 2*BN*SV)            // 42752
#define SMEM_FLOATS (PS_OFF + BM*SP)         // 51456
#define SMEM_BYTES (SMEM_FLOATS*4)           // 205824

// ---------------- device scratch ----------------
__device__ unsigned g_mask_bits[SEQ * (SEQ / 32)];   // 2 MB packed mask
__device__ float    g_v1sum[NH * HD];                // sum_t V[1,h,t,d]

// ---------------- helpers ----------------
__device__ __forceinline__ float to_tf32(float x) {
    float y; asm("cvt.rna.tf32.f32 %0, %1;" : "=f"(y) : "f"(x)); return y;
}
__device__ __forceinline__ float ex2_fast(float x) {
    float y; asm("ex2.approx.f32 %0, %1;" : "=f"(y) : "f"(x)); return y;
}
__device__ __forceinline__ float rcp_fast(float x) {
    float y; asm("rcp.approx.f32 %0, %1;" : "=f"(y) : "f"(x)); return y;
}
__device__ __forceinline__ float sigp(float d) {
    // p0 = 1/(1+exp(-0.125*d)) ; C = -0.125*log2(e)
    const float C = -0.18033688011111652f;
    return rcp_fast(1.0f + ex2_fast(d * C));
}

#define MMA_TF32(d, a, b) asm volatile( \
    "mma.sync.aligned.m16n8k8.row.col.f32.tf32.tf32.f32 " \
    "{%0,%1,%2,%3}, {%4,%5,%6,%7}, {%8,%9}, {%0,%1,%2,%3};" \
    : "+f"((d)[0]), "+f"((d)[1]), "+f"((d)[2]), "+f"((d)[3]) \
    : "r"(__float_as_uint((a)[0])), "r"(__float_as_uint((a)[1])), \
      "r"(__float_as_uint((a)[2])), "r"(__float_as_uint((a)[3])), \
      "r"(__float_as_uint((b)[0])), "r"(__float_as_uint((b)[1])))

// ---------------- prologue kernels ----------------
__global__ void pack_mask_kernel(const int* __restrict__ mask) {
    int w = blockIdx.x * blockDim.x + threadIdx.x;      // 0 .. SEQ*128-1
    const int4* src = (const int4*)(mask + (size_t)w * 32);
    unsigned bits = 0;
    #pragma unroll
    for (int g = 0; g < 8; g++) {
        int4 v = src[g];
        bits |= (v.x != 0 ? 1u : 0u) << (g * 4 + 0);
        bits |= (v.y != 0 ? 1u : 0u) << (g * 4 + 1);
        bits |= (v.z != 0 ? 1u : 0u) << (g * 4 + 2);
        bits |= (v.w != 0 ? 1u : 0u) << (g * 4 + 3);
    }
    g_mask_bits[w] = bits;
}

__global__ void v1sum_kernel(const float* __restrict__ v) {
    __shared__ float red[256];
    int h = blockIdx.x;
    int d = threadIdx.x & 63;
    int part = threadIdx.x >> 6;
    float s = 0.f;
    for (int t = part; t < SEQ; t += 4)
        s += v[(((size_t)NH + h) * SEQ + t) * HD + d];   // b=1
    red[threadIdx.x] = s;
    __syncthreads();
    if (part == 0)
        g_v1sum[h * HD + d] = red[d] + red[64 + d] + red[128 + d] + red[192 + d];
}

// ---------------- main kernel ----------------
__global__ __launch_bounds__(NTH, 1)
void sdpa_mma_kernel(const float* __restrict__ q,
                     const float* __restrict__ k,
                     const float* __restrict__ v,
                     float* __restrict__ out,
                     float* __restrict__ attn)
{
    extern __shared__ float sm[];
    float* Qs = sm + QS_OFF;   // [128][SQ]  cols 0:64 = q0, 64:128 = -q1
    float* Ks = sm + KS_OFF;   // [64][SQ]   cols 0:64 = k0, 64:128 = k1
    float* Vs = sm + VS_OFF;   // 2 x [64][SV]  cols 0:64 = v0, 64:128 = v1
    float* Ps = sm + PS_OFF;   // [128][SP]  p0 (tf32)

    const int h   = blockIdx.y;
    const int s0  = blockIdx.x * BM;
    const int tid = threadIdx.x;
    const int w    = tid >> 5;
    const int lane = tid & 31;
    const int gr  = lane >> 2;     // group id (0..7)
    const int ct  = lane & 3;      // thread-in-group
    const int wm  = w >> 1;        // warp m-block (16 rows) 0..7
    const int wn  = w & 1;         // warp n-block 0..1

    // staging identity (constant per thread)
    const int pr0 = tid >> 5;      // 0..15 (row base; +16j)
    const int pc4 = tid & 31;      // float4 column 0..31
    const int pb  = pc4 >> 4;      // batch half
    const int pd4 = pc4 & 15;      // d float4 idx
    const size_t bh  = ((size_t)pb * NH + h) * SEQ;
    const float* kbase = k + (bh + pr0) * HD + pd4 * 4;
    const float* vbase = v + (bh + pr0) * HD + pd4 * 4;

    // ---- prefetch tile 0 into registers ----
    float4 kreg[4], vreg[4];
    #pragma unroll
    for (int j = 0; j < 4; j++) {
        kreg[j] = *(const float4*)(kbase + (size_t)(j * 16) * HD);
        vreg[j] = *(const float4*)(vbase + (size_t)(j * 16) * HD);
    }

    // ---- stage Q (once): A = [q0 | -q1], tf32 ----
    {
        const float sgn = pb ? -1.f : 1.f;
        #pragma unroll
        for (int j = 0; j < 8; j++) {
            int row = pr0 + 16 * j;
            float4 val = *(const float4*)(q + (bh + s0 + row) * HD + pd4 * 4);
            float4 o;
            o.x = to_tf32(sgn * val.x); o.y = to_tf32(sgn * val.y);
            o.z = to_tf32(sgn * val.z); o.w = to_tf32(sgn * val.w);
            *(float4*)(Qs + row * SQ + pc4 * 4) = o;
        }
    }

    // ---- persistent O accumulators: warp tile 16 rows x 64 cols ----
    float oc[8][4];
    #pragma unroll
    for (int nt = 0; nt < 8; nt++)
        #pragma unroll
        for (int u = 0; u < 4; u++) oc[nt][u] = 0.f;

    const int r = wm * 16 + gr;        // this thread's base row (0..127)
    float* attn1 = attn + (size_t)NH * SEQ * SEQ;

    for (int it = 0; it < ITERS; ++it) {
        const int t0  = it * BN;
        const int buf = (it & 1) * BN * SV;

        // ---- commit prefetched tile it to smem (tf32 rna) ----
        #pragma unroll
        for (int j = 0; j < 4; j++) {
            int rr = pr0 + 16 * j;
            float4 kv = kreg[j];
            float4 ko;
            ko.x = to_tf32(kv.x); ko.y = to_tf32(kv.y);
            ko.z = to_tf32(kv.z); ko.w = to_tf32(kv.w);
            *(float4*)(Ks + rr * SQ + pc4 * 4) = ko;
            float4 vv = vreg[j];
            float4 vo;
            vo.x = to_tf32(vv.x); vo.y = to_tf32(vv.y);
            vo.z = to_tf32(vv.z); vo.w = to_tf32(vv.w);
            *(float4*)(Vs + buf + rr * SV + pc4 * 4) = vo;
        }
        __syncthreads();

        // ---- issue prefetch for tile it+1 (consumed next iteration) ----
        if (it + 1 < ITERS) {
            const size_t roff = (size_t)(t0 + BN) * HD;
            #pragma unroll
            for (int j = 0; j < 4; j++) {
                kreg[j] = *(const float4*)(kbase + roff + (size_t)(j * 16) * HD);
                vreg[j] = *(const float4*)(vbase + roff + (size_t)(j * 16) * HD);
            }
        }

        // ---- MMA1: Delta[128][64] = [q|-q] * [k0|k1]^T ; warp tile 16x32 ----
        float sc[4][4];
        #pragma unroll
        for (int nt = 0; nt < 4; nt++)
            #pragma unroll
            for (int u = 0; u < 4; u++) sc[nt][u] = 0.f;

        #pragma unroll
        for (int kk = 0; kk < 16; kk++) {
            const int k0 = kk * 8;
            float a[4];
            a[0] = Qs[r * SQ + k0 + ct];
            a[1] = Qs[(r + 8) * SQ + k0 + ct];
            a[2] = Qs[r * SQ + k0 + ct + 4];
            a[3] = Qs[(r + 8) * SQ + k0 + ct + 4];
            float bfr[4][2];
            #pragma unroll
            for (int nt = 0; nt < 4; nt++) {
                int t = wn * 32 + nt * 8 + gr;
                bfr[nt][0] = Ks[t * SQ + k0 + ct];
                bfr[nt][1] = Ks[t * SQ + k0 + ct + 4];
            }
            #pragma unroll
            for (int nt = 0; nt < 4; nt++)
                MMA_TF32(sc[nt], a, bfr[nt]);
        }

        // ---- epilogue: sigmoid + mask ; stage P (tf32) ----
        {
            unsigned mw0 = g_mask_bits[(size_t)(s0 + r) * 128 + it * 2 + wn];
            unsigned mw1 = g_mask_bits[(size_t)(s0 + r + 8) * 128 + it * 2 + wn];
            #pragma unroll
            for (int nt = 0; nt < 4; nt++) {
                int cl = nt * 8 + ct * 2;          // col within warp's 32
                float* s = sc[nt];
                float p00 = ((mw0 >> cl) & 1)       ? 0.5f : sigp(s[0]);
                float p01 = ((mw0 >> (cl + 1)) & 1) ? 0.5f : sigp(s[1]);
                float p10 = ((mw1 >> cl) & 1)       ? 0.5f : sigp(s[2]);
                float p11 = ((mw1 >> (cl + 1)) & 1) ? 0.5f : sigp(s[3]);
                int pc = wn * 32 + cl;
                *(float2*)(Ps + r * SP + pc) =
                    make_float2(to_tf32(p00), to_tf32(p01));
                *(float2*)(Ps + (r + 8) * SP + pc) =
                    make_float2(to_tf32(p10), to_tf32(p11));
            }
        }
        __syncthreads();

        // ---- attn stores: coalesced STG.128 from Ps readback ----
        {
            const int rr = tid >> 4;          // 0..31
            const int c4 = tid & 15;          // 0..15 (full 64-float row)
            #pragma unroll
            for (int j = 0; j < 4; j++) {
                int row = j * 32 + rr;
                float4 p4 = *(const float4*)(Ps + row * SP + c4 * 4);
                size_t ab = ((size_t)h * SEQ + s0 + row) * SEQ + t0 + c4 * 4;
                *(float4*)(attn + ab) = p4;
                float4 q4;
                q4.x = 1.f - p4.x; q4.y = 1.f - p4.y;
                q4.z = 1.f - p4.z; q4.w = 1.f - p4.w;
                *(float4*)(attn1 + ab) = q4;
            }
        }

        // ---- MMA2: O[128][128] += P0 * [V0|V1] ; warp tile 16x64 ----
        #pragma unroll
        for (int kk = 0; kk < 8; kk++) {
            const int k0 = kk * 8;
            float a[4];
            a[0] = Ps[r * SP + k0 + ct];
            a[1] = Ps[(r + 8) * SP + k0 + ct];
            a[2] = Ps[r * SP + k0 + ct + 4];
            a[3] = Ps[(r + 8) * SP + k0 + ct + 4];
            float bfr[8][2];
            #pragma unroll
            for (int nt = 0; nt < 8; nt++) {
                int n = wn * 64 + nt * 8 + gr;
                bfr[nt][0] = Vs[buf + (k0 + ct) * SV + n];
                bfr[nt][1] = Vs[buf + (k0 + ct + 4) * SV + n];
            }
            #pragma unroll
            for (int nt = 0; nt < 8; nt++)
                MMA_TF32(oc[nt], a, bfr[nt]);
        }
    }

    // ---- final out write: wn=0 -> b0 = acc ; wn=1 -> b1 = v1sum - acc ----
    const float* vs = g_v1sum + h * HD;
    #pragma unroll
    for (int nt = 0; nt < 8; nt++) {
        int n = wn * 64 + nt * 8 + ct * 2;   // 0..127
        int d = n & 63;
        float* c = oc[nt];
        float2 w0, w1;
        if (wn == 0) {
            w0 = make_float2(c[0], c[1]);
            w1 = make_float2(c[2], c[3]);
        } else {
            w0 = make_float2(vs[d] - c[0], vs[d + 1] - c[1]);
            w1 = make_float2(vs[d] - c[2], vs[d + 1] - c[3]);
        }
        size_t ob = (((size_t)wn * NH + h) * SEQ + s0 + r) * HD + d;
        *(float2*)(out + ob)          = w0;
        *(float2*)(out + ob + 8 * HD) = w1;
    }
}

// ---------------- launcher ----------------
extern "C" void kernel_launch(void* const* d_in, const int* in_sizes, int n_in,
                              void* d_out, int out_size)
{
    const float* q    = (const float*)d_in[0];
    const float* k    = (const float*)d_in[1];
    const float* v    = (const float*)d_in[2];
    const int*   mask = (const int*)  d_in[3];

    float* out  = (float*)d_out;
    float* attn = out + (size_t)2 * NH * SEQ * HD;

    pack_mask_kernel<<<SEQ * 128 / 256, 256>>>(mask);
    v1sum_kernel<<<NH, 256>>>(v);

    cudaFuncSetAttribute(sdpa_mma_kernel,
                         cudaFuncAttributeMaxDynamicSharedMemorySize, SMEM_BYTES);
    dim3 grid(SEQ / BM, NH);
    sdpa_mma_kernel<<<grid, NTH, SMEM_BYTES>>>(q, k, v, out, attn);
}

// round 9
// speedup vs baseline: 1.3913x; 1.1725x over previous
#include <cuda_runtime.h>
#include <cuda_fp16.h>
#include <cstdint>

// ---------------- problem constants ----------------
#define SEQ   4096
#define HD    64
#define NH    4
#define BM    128          // s rows per CTA
#define BN    64           // t cols per iteration
#define NTH   512
#define ITERS (SEQ/BN)     // 64

// smem strides (in halves): 136*2=272B (68 words ≡ 4 mod 32 banks)
#define SQH 136            // Qs/Ks/Vs row stride
#define SPH 72             // Ps row stride (144B = 36 words ≡ 4 mod 32)

// smem byte offsets
#define QS_OFF 0
#define KS_OFF (QS_OFF + BM*SQH*2)        // 34816
#define VS_OFF (KS_OFF + BN*SQH*2)        // 52224
#define PS_OFF (VS_OFF + 2*BN*SQH*2)      // 87040
#define SMEM_BYTES (PS_OFF + BM*SPH*2)    // 105472
#define VBUF_BYTES (BN*SQH*2)             // 17408

// ---------------- device scratch ----------------
__device__ unsigned g_mask_bits[SEQ * (SEQ / 32)];   // 2 MB packed mask
__device__ float    g_v1sum[NH * HD];                // sum_t V[1,h,t,d]

// ---------------- helpers ----------------
__device__ __forceinline__ float ex2_fast(float x) {
    float y; asm("ex2.approx.f32 %0, %1;" : "=f"(y) : "f"(x)); return y;
}
__device__ __forceinline__ float rcp_fast(float x) {
    float y; asm("rcp.approx.f32 %0, %1;" : "=f"(y) : "f"(x)); return y;
}
__device__ __forceinline__ float sigp(float d) {
    // p0 = 1/(1+exp(-0.125*d)) ; C = -0.125*log2(e)
    const float C = -0.18033688011111652f;
    return rcp_fast(1.0f + ex2_fast(d * C));
}
__device__ __forceinline__ uint32_t f22u(float a, float b) {
    __half2 h = __floats2half2_rn(a, b);
    return *(uint32_t*)&h;
}
__device__ __forceinline__ uint32_t smem_u32(const void* p) {
    uint32_t a;
    asm("{ .reg .u64 t; cvta.to.shared.u64 t, %1; cvt.u32.u64 %0, t; }" : "=r"(a) : "l"(p));
    return a;
}

#define LDSM_X4(r, addr) asm volatile( \
    "ldmatrix.sync.aligned.m8n8.x4.shared.b16 {%0,%1,%2,%3}, [%4];" \
    : "=r"((r)[0]), "=r"((r)[1]), "=r"((r)[2]), "=r"((r)[3]) : "r"(addr))

#define LDSM_X4T(r, addr) asm volatile( \
    "ldmatrix.sync.aligned.m8n8.x4.trans.shared.b16 {%0,%1,%2,%3}, [%4];" \
    : "=r"((r)[0]), "=r"((r)[1]), "=r"((r)[2]), "=r"((r)[3]) : "r"(addr))

#define MMA16816(d, a, b0, b1) asm volatile( \
    "mma.sync.aligned.m16n8k16.row.col.f32.f16.f16.f32 " \
    "{%0,%1,%2,%3}, {%4,%5,%6,%7}, {%8,%9}, {%0,%1,%2,%3};" \
    : "+f"((d)[0]), "+f"((d)[1]), "+f"((d)[2]), "+f"((d)[3]) \
    : "r"((a)[0]), "r"((a)[1]), "r"((a)[2]), "r"((a)[3]), "r"(b0), "r"(b1))

// ---------------- prologue kernels ----------------
__global__ void pack_mask_kernel(const int* __restrict__ mask) {
    int w = blockIdx.x * blockDim.x + threadIdx.x;      // 0 .. SEQ*128-1
    const int4* src = (const int4*)(mask + (size_t)w * 32);
    unsigned bits = 0;
    #pragma unroll
    for (int g = 0; g < 8; g++) {
        int4 v = src[g];
        bits |= (v.x != 0 ? 1u : 0u) << (g * 4 + 0);
        bits |= (v.y != 0 ? 1u : 0u) << (g * 4 + 1);
        bits |= (v.z != 0 ? 1u : 0u) << (g * 4 + 2);
        bits |= (v.w != 0 ? 1u : 0u) << (g * 4 + 3);
    }
    g_mask_bits[w] = bits;
}

__global__ void v1sum_kernel(const float* __restrict__ v) {
    __shared__ float red[256];
    int h = blockIdx.x;
    int d = threadIdx.x & 63;
    int part = threadIdx.x >> 6;
    float s = 0.f;
    for (int t = part; t < SEQ; t += 4)
        s += v[(((size_t)NH + h) * SEQ + t) * HD + d];   // b=1
    red[threadIdx.x] = s;
    __syncthreads();
    if (part == 0)
        g_v1sum[h * HD + d] = red[d] + red[64 + d] + red[128 + d] + red[192 + d];
}

// ---------------- main kernel ----------------
__global__ __launch_bounds__(NTH, 1)
void sdpa_mma_kernel(const float* __restrict__ q,
                     const float* __restrict__ k,
                     const float* __restrict__ v,
                     float* __restrict__ out,
                     float* __restrict__ attn)
{
    extern __shared__ char sm[];
    const uint32_t smb = smem_u32(sm);

    const int h   = blockIdx.y;
    const int s0  = blockIdx.x * BM;
    const int tid = threadIdx.x;
    const int w    = tid >> 5;
    const int lane = tid & 31;
    const int gr  = lane >> 2;     // group id (0..7)
    const int ct  = lane & 3;      // thread-in-group
    const int wm  = w & 3;         // warp m-group (32 rows)
    const int wn  = w >> 2;        // warp n-group

    // staging identity
    const int pr0 = tid >> 5;      // 0..15 (row base; +16j)
    const int pc4 = tid & 31;      // float4 column 0..31 (covers 128 concat cols)
    const int pb  = pc4 >> 4;      // batch half
    const int pd4 = pc4 & 15;      // d float4 idx
    const size_t bh = ((size_t)pb * NH + h) * SEQ;
    const float* kbase = k + (bh + pr0) * HD + pd4 * 4;
    const float* vbase = v + (bh + pr0) * HD + pd4 * 4;

    // ---- prefetch tile 0 into registers ----
    float4 kreg[4], vreg[4];
    #pragma unroll
    for (int j = 0; j < 4; j++) {
        kreg[j] = *(const float4*)(kbase + (size_t)(j * 16) * HD);
        vreg[j] = *(const float4*)(vbase + (size_t)(j * 16) * HD);
    }

    // ---- stage Q (once): A = [q0 | -q1], fp16 ----
    {
        const float sgn = pb ? -1.f : 1.f;
        #pragma unroll
        for (int j = 0; j < 8; j++) {
            int row = pr0 + 16 * j;
            float4 val = *(const float4*)(q + (bh + s0 + row) * HD + pd4 * 4);
            uint2 o;
            o.x = f22u(sgn * val.x, sgn * val.y);
            o.y = f22u(sgn * val.z, sgn * val.w);
            *(uint2*)(sm + QS_OFF + row * (SQH*2) + pc4 * 8) = o;
        }
    }

    // ---- ldmatrix lane-address bases (byte offsets into smem) ----
    // MMA1 A (Qs, non-trans): rows wm*32+(lane&15)(+16 mt), halfcol kk*16+(lane>>4)*8
    const uint32_t qa = smb + QS_OFF + (wm*32 + (lane & 15)) * (SQH*2) + (lane >> 4) * 16;
    // MMA1 B (Ks, non-trans): rows wn*16+(lane&7)+(lane>>4)*8, halfcol kk*16+((lane>>3)&1)*8
    const uint32_t kb = smb + KS_OFF + (wn*16 + (lane & 7) + (lane >> 4) * 8) * (SQH*2)
                        + ((lane >> 3) & 1) * 16;
    // MMA2 A (Ps, non-trans): rows wm*32+(lane&15)(+16 mt), halfcol kk*16+(lane>>4)*8
    const uint32_t pa = smb + PS_OFF + (wm*32 + (lane & 15)) * (SPH*2) + (lane >> 4) * 16;
    // MMA2 B (Vs, trans): rows kk*16+(lane&7)+((lane>>3)&1)*8, halfcol wn*32+(lane>>4)*8 (+16)
    const uint32_t vbrow = ((lane & 7) + ((lane >> 3) & 1) * 8) * (SQH*2);
    const uint32_t vbcol = (wn*32 + (lane >> 4) * 8) * 2;

    // ---- persistent O accumulators: warp tile 32 rows x 32 cols ----
    float oc[2][4][4];
    #pragma unroll
    for (int mt = 0; mt < 2; mt++)
        #pragma unroll
        for (int nt = 0; nt < 4; nt++)
            #pragma unroll
            for (int u = 0; u < 4; u++) oc[mt][nt][u] = 0.f;

    float* attn1 = attn + (size_t)NH * SEQ * SEQ;

    for (int it = 0; it < ITERS; ++it) {
        const int t0  = it * BN;
        const uint32_t buf = (it & 1) * VBUF_BYTES;

        // ---- commit prefetched tile it to smem (fp16) ----
        #pragma unroll
        for (int j = 0; j < 4; j++) {
            int rr = pr0 + 16 * j;
            uint2 ko, vo;
            ko.x = f22u(kreg[j].x, kreg[j].y); ko.y = f22u(kreg[j].z, kreg[j].w);
            vo.x = f22u(vreg[j].x, vreg[j].y); vo.y = f22u(vreg[j].z, vreg[j].w);
            *(uint2*)(sm + KS_OFF + rr * (SQH*2) + pc4 * 8) = ko;
            *(uint2*)(sm + VS_OFF + buf + rr * (SQH*2) + pc4 * 8) = vo;
        }
        __syncthreads();

        // ---- issue prefetch for tile it+1 ----
        if (it + 1 < ITERS) {
            const size_t roff = (size_t)(t0 + BN) * HD;
            #pragma unroll
            for (int j = 0; j < 4; j++) {
                kreg[j] = *(const float4*)(kbase + roff + (size_t)(j * 16) * HD);
                vreg[j] = *(const float4*)(vbase + roff + (size_t)(j * 16) * HD);
            }
        }

        // ---- MMA1: Delta[128][64] = [q0|-q1] * [k0|k1]^T ; warp tile 32x16 ----
        float sc[2][2][4];
        #pragma unroll
        for (int mt = 0; mt < 2; mt++)
            #pragma unroll
            for (int nt = 0; nt < 2; nt++)
                #pragma unroll
                for (int u = 0; u < 4; u++) sc[mt][nt][u] = 0.f;

        #pragma unroll
        for (int kk = 0; kk < 8; kk++) {
            uint32_t a0[4], a1[4], b[4];
            LDSM_X4(a0, qa + kk * 32);
            LDSM_X4(a1, qa + kk * 32 + 16 * (SQH*2));
            LDSM_X4(b,  kb + kk * 32);
            MMA16816(sc[0][0], a0, b[0], b[1]);
            MMA16816(sc[0][1], a0, b[2], b[3]);
            MMA16816(sc[1][0], a1, b[0], b[1]);
            MMA16816(sc[1][1], a1, b[2], b[3]);
        }

        // ---- epilogue: sigmoid + mask ; stage P (fp16) ----
        #pragma unroll
        for (int mt = 0; mt < 2; mt++) {
            #pragma unroll
            for (int u = 0; u < 2; u++) {
                int row = wm*32 + mt*16 + gr + 8*u;
                unsigned mw = g_mask_bits[(size_t)(s0 + row) * 128 + it * 2 + (wn >> 1)];
                #pragma unroll
                for (int nt = 0; nt < 2; nt++) {
                    int bitb = (wn & 1) * 16 + nt * 8 + 2 * ct;
                    float d0 = sc[mt][nt][2*u + 0];
                    float d1 = sc[mt][nt][2*u + 1];
                    float p0 = ((mw >> bitb) & 1)       ? 0.5f : sigp(d0);
                    float p1 = ((mw >> (bitb + 1)) & 1) ? 0.5f : sigp(d1);
                    *(uint32_t*)(sm + PS_OFF + row * (SPH*2)
                                 + (wn*16 + nt*8 + 2*ct) * 2) = f22u(p0, p1);
                }
            }
        }
        __syncthreads();

        // ---- attn stores: coalesced, from Ps readback (half -> f32) ----
        {
            const int g  = tid & 7;            // 8-half group
            const int rr = tid >> 3;           // 0..63
            #pragma unroll
            for (int j = 0; j < 2; j++) {
                int row = j * 64 + rr;
                uint4 u4 = *(uint4*)(sm + PS_OFF + row * (SPH*2) + g * 16);
                float2 f0 = __half22float2(*(__half2*)&u4.x);
                float2 f1 = __half22float2(*(__half2*)&u4.y);
                float2 f2 = __half22float2(*(__half2*)&u4.z);
                float2 f3 = __half22float2(*(__half2*)&u4.w);
                size_t ab = ((size_t)h * SEQ + s0 + row) * SEQ + t0 + g * 8;
                float4 wa = make_float4(f0.x, f0.y, f1.x, f1.y);
                float4 wb = make_float4(f2.x, f2.y, f3.x, f3.y);
                *(float4*)(attn + ab)     = wa;
                *(float4*)(attn + ab + 4) = wb;
                float4 qa4 = make_float4(1.f - f0.x, 1.f - f0.y, 1.f - f1.x, 1.f - f1.y);
                float4 qb4 = make_float4(1.f - f2.x, 1.f - f2.y, 1.f - f3.x, 1.f - f3.y);
                *(float4*)(attn1 + ab)     = qa4;
                *(float4*)(attn1 + ab + 4) = qb4;
            }
        }

        // ---- MMA2: O[128][128] += P0 * [V0|V1] ; warp tile 32x32 ----
        #pragma unroll
        for (int kk = 0; kk < 4; kk++) {
            uint32_t a0[4], a1[4], bA[4], bB[4];
            LDSM_X4(a0, pa + kk * 32);
            LDSM_X4(a1, pa + kk * 32 + 16 * (SPH*2));
            uint32_t vaddr = smb + VS_OFF + buf + vbrow + vbcol + (uint32_t)kk * 16 * (SQH*2);
            LDSM_X4T(bA, vaddr);
            LDSM_X4T(bB, vaddr + 32);
            MMA16816(oc[0][0], a0, bA[0], bA[1]);
            MMA16816(oc[0][1], a0, bA[2], bA[3]);
            MMA16816(oc[0][2], a0, bB[0], bB[1]);
            MMA16816(oc[0][3], a0, bB[2], bB[3]);
            MMA16816(oc[1][0], a1, bA[0], bA[1]);
            MMA16816(oc[1][1], a1, bA[2], bA[3]);
            MMA16816(oc[1][2], a1, bB[0], bB[1]);
            MMA16816(oc[1][3], a1, bB[2], bB[3]);
        }
    }

    // ---- final out write: wn 0,1 -> b0 = acc ; wn 2,3 -> b1 = v1sum - acc ----
    const float* vs = g_v1sum + h * HD;
    const int b = wn >> 1;
    #pragma unroll
    for (int mt = 0; mt < 2; mt++) {
        int row = s0 + wm*32 + mt*16 + gr;
        #pragma unroll
        for (int nt = 0; nt < 4; nt++) {
            int n0 = wn*32 + nt*8 + 2*ct;
            int d  = n0 & 63;
            float* c = oc[mt][nt];
            float2 w0, w1;
            if (b == 0) {
                w0 = make_float2(c[0], c[1]);
                w1 = make_float2(c[2], c[3]);
            } else {
                w0 = make_float2(vs[d] - c[0], vs[d + 1] - c[1]);
                w1 = make_float2(vs[d] - c[2], vs[d + 1] - c[3]);
            }
            size_t ob = (((size_t)b * NH + h) * SEQ + row) * HD + d;
            *(float2*)(out + ob)          = w0;
            *(float2*)(out + ob + 8 * HD) = w1;
        }
    }
}

// ---------------- launcher ----------------
extern "C" void kernel_launch(void* const* d_in, const int* in_sizes, int n_in,
                              void* d_out, int out_size)
{
    const float* q    = (const float*)d_in[0];
    const float* k    = (const float*)d_in[1];
    const float* v    = (const float*)d_in[2];
    const int*   mask = (const int*)  d_in[3];

    float* out  = (float*)d_out;
    float* attn = out + (size_t)2 * NH * SEQ * HD;

    pack_mask_kernel<<<SEQ * 128 / 256, 256>>>(mask);
    v1sum_kernel<<<NH, 256>>>(v);

    cudaFuncSetAttribute(sdpa_mma_kernel,
                         cudaFuncAttributeMaxDynamicSharedMemorySize, SMEM_BYTES);
    dim3 grid(SEQ / BM, NH);
    sdpa_mma_kernel<<<grid, NTH, SMEM_BYTES>>>(q, k, v, out, attn);
}